// round 10
// baseline (speedup 1.0000x reference)
#include <cuda_runtime.h>
#include <cuda_bf16.h>
#include <cstdint>

// Problem constants
#define NN   50000
#define EE   600000
#define HH   128
#define LL   4
#define GG   64
#define EMBD 64
#define CC   10
#define LH   (LL*HH)        // 512
#define ZIN  (LH+EMBD)      // 576
#define H1D  256            // 2*H
#define BN_EPS 1e-5f
#define STR  136            // smem row stride in bf16 elems (multiple of 8)

// ---------------- device scratch (static, allocation-guard safe) -------------
__device__ __align__(16) float g_agg[NN*HH];   // aggregated input of current layer
__device__ __align__(16) float g_x[NN*HH];     // layer output (next layer's x)
__device__ __align__(16) float g_h2[NN*HH];    // pre-BN activations
__device__ __align__(16) float g_bnsum[2*HH];  // per-col sum / sumsq
__device__ __align__(16) float g_pool[GG*ZIN]; // pooled sums
__device__ __align__(16) float g_cnt[GG];      // nodes per graph
// CSR (rebuilt every call — deterministic)
__device__ int g_rowptr[NN+1];
__device__ int g_cursor[NN];
__device__ int g_col[EE];

// ---------------- helpers ----------------------------------------------------
__device__ __forceinline__ void red_add_v4(float* p, float4 v) {
    asm volatile("red.global.add.v4.f32 [%0], {%1,%2,%3,%4};"
                 :: "l"(p), "f"(v.x), "f"(v.y), "f"(v.z), "f"(v.w)
                 : "memory");
}
__device__ __forceinline__ uint32_t sptr(const void* p) {
    return (uint32_t)__cvta_generic_to_shared(p);
}
__device__ __forceinline__ void ldmx4(uint32_t* r, uint32_t addr) {
    asm volatile("ldmatrix.sync.aligned.m8n8.x4.shared.b16 {%0,%1,%2,%3}, [%4];"
        : "=r"(r[0]), "=r"(r[1]), "=r"(r[2]), "=r"(r[3]) : "r"(addr));
}
__device__ __forceinline__ void ldmx4t(uint32_t* r, uint32_t addr) {
    asm volatile("ldmatrix.sync.aligned.m8n8.x4.trans.shared.b16 {%0,%1,%2,%3}, [%4];"
        : "=r"(r[0]), "=r"(r[1]), "=r"(r[2]), "=r"(r[3]) : "r"(addr));
}
__device__ __forceinline__ void mma16816(float* c, const uint32_t* a, const uint32_t* b) {
    asm volatile("mma.sync.aligned.m16n8k16.row.col.f32.bf16.bf16.f32 "
        "{%0,%1,%2,%3}, {%4,%5,%6,%7}, {%8,%9}, {%0,%1,%2,%3};"
        : "+f"(c[0]), "+f"(c[1]), "+f"(c[2]), "+f"(c[3])
        : "r"(a[0]), "r"(a[1]), "r"(a[2]), "r"(a[3]), "r"(b[0]), "r"(b[1]));
}
__device__ __forceinline__ uint32_t pack_bf2(__nv_bfloat16 lo16, __nv_bfloat16 hi16) {
    return ((uint32_t)__bfloat16_as_ushort(hi16) << 16) | __bfloat16_as_ushort(lo16);
}
// split x into bf16 hi + bf16 lo (x ≈ hi + lo)
__device__ __forceinline__ void split_bf(float x, __nv_bfloat16& h, __nv_bfloat16& l) {
    h = __float2bfloat16(x);
    l = __float2bfloat16(x - __bfloat162float(h));
}

// ---------------- zero / CSR build kernels -----------------------------------
__global__ void k_zero_pool() {
    int i = blockIdx.x * blockDim.x + threadIdx.x;
    if (i < GG*ZIN) g_pool[i] = 0.f;
    if (i < GG)     g_cnt[i]  = 0.f;
}
__global__ void k_zero_bn() {
    if (threadIdx.x < 2*HH) g_bnsum[threadIdx.x] = 0.f;
}
__global__ void k_zero_rp() {
    int i = blockIdx.x * blockDim.x + threadIdx.x;
    if (i < NN+1) g_rowptr[i] = 0;
}
__global__ void k_deg(const int* __restrict__ ei) {
    int e = blockIdx.x * blockDim.x + threadIdx.x;
    if (e < EE) atomicAdd(&g_rowptr[ei[EE + e] + 1], 1);
}
__global__ __launch_bounds__(1024)
void k_scan() {
    __shared__ int carry;
    __shared__ int warpsum[32];
    int tid = threadIdx.x, lane = tid & 31, w = tid >> 5;
    if (tid == 0) carry = 0;
    __syncthreads();
    for (int base = 0; base < NN+1; base += 1024) {
        int i = base + tid;
        int v = (i <= NN) ? g_rowptr[i] : 0;
        int s = v;
#pragma unroll
        for (int o = 1; o < 32; o <<= 1) {
            int t = __shfl_up_sync(0xFFFFFFFFu, s, o);
            if (lane >= o) s += t;
        }
        if (lane == 31) warpsum[w] = s;
        __syncthreads();
        if (w == 0) {
            int ws = warpsum[lane];
#pragma unroll
            for (int o = 1; o < 32; o <<= 1) {
                int t = __shfl_up_sync(0xFFFFFFFFu, ws, o);
                if (lane >= o) ws += t;
            }
            warpsum[lane] = ws;
        }
        __syncthreads();
        int incl = s + (w ? warpsum[w-1] : 0) + carry;
        if (i <= NN) g_rowptr[i] = incl;
        if (i <  NN) g_cursor[i] = incl;
        int total = warpsum[31] + carry;
        __syncthreads();
        if (tid == 0) carry = total;
        __syncthreads();
    }
}
__global__ void k_fill(const int* __restrict__ ei) {
    int e = blockIdx.x * blockDim.x + threadIdx.x;
    if (e >= EE) return;
    int d = ei[EE + e];
    int pos = atomicAdd(&g_cursor[d], 1);
    g_col[pos] = ei[e];
}

// ---------------- gather: agg[i] = (1+eps_l)*x[i] + sum_{j in nbr(i)} x[j] ---
__global__ void k_gather(const float* __restrict__ x,
                         const float* __restrict__ eps, int l) {
    int gtid = blockIdx.x * blockDim.x + threadIdx.x;
    int row  = gtid >> 5;
    int lane = gtid & 31;
    if (row >= NN) return;
    const float4* x4 = (const float4*)x;
    float s = 1.0f + eps[l];
    float4 acc = x4[(size_t)row*32 + lane];
    acc.x *= s; acc.y *= s; acc.z *= s; acc.w *= s;

    int e   = g_rowptr[row];
    int end = g_rowptr[row+1];
    for (; e + 1 < end; e += 2) {
        int s0 = g_col[e], s1 = g_col[e+1];
        float4 v0 = x4[(size_t)s0*32 + lane];
        float4 v1 = x4[(size_t)s1*32 + lane];
        acc.x += v0.x + v1.x;
        acc.y += v0.y + v1.y;
        acc.z += v0.z + v1.z;
        acc.w += v0.w + v1.w;
    }
    if (e < end) {
        int s0 = g_col[e];
        float4 v0 = x4[(size_t)s0*32 + lane];
        acc.x += v0.x; acc.y += v0.y; acc.z += v0.z; acc.w += v0.w;
    }
    *(float4*)(g_agg + (size_t)row*HH + lane*4) = acc;
}

// ---------------- fused double GEMM via bf16 tensor cores (3-term split) -----
// h1 = relu(A @ W1 + b1) kept in smem (bf16 hi/lo), C = relu(h1 @ W2 + b2) + BN stats.
// Block: 128 rows x 128 cols, 256 threads = 8 warps (4x2), warp tile 32x64.
__global__ __launch_bounds__(256)
void k_gemm_fused(const float* __restrict__ A,
                  const float* __restrict__ W1g, const float* __restrict__ bias1,
                  const float* __restrict__ W2g, const float* __restrict__ bias2,
                  float* __restrict__ C) {
    extern __shared__ char smem_raw[];
    __nv_bfloat16* A_hi = (__nv_bfloat16*)smem_raw;          // [128][STR]
    __nv_bfloat16* A_lo = A_hi + 128*STR;
    __nv_bfloat16* W_hi = A_lo + 128*STR;
    __nv_bfloat16* W_lo = W_hi + 128*STR;
    float* ssum = (float*)(W_lo + 128*STR);                  // 128
    float* ssq  = ssum + 128;                                // 128

    const int tid  = threadIdx.x;
    const int lane = tid & 31;
    const int wid  = tid >> 5;
    const int warpM = wid & 3;         // 0..3 -> rows warpM*32
    const int warpN = wid >> 2;        // 0..1 -> cols warpN*64
    const int blockRow = blockIdx.x * 128;

    if (tid < 128) { ssum[tid] = 0.f; ssq[tid] = 0.f; }

    // ---- convert A (agg) fp32 -> bf16 hi/lo in smem ----
    {
        int row  = tid >> 1;
        int cb   = (tid & 1) * 64;
        int grow = blockRow + row;
        bool ok  = (grow < NN);
        const float* src = A + (size_t)grow*HH + cb;
#pragma unroll
        for (int c = 0; c < 64; c += 4) {
            float4 v = ok ? *(const float4*)(src + c) : make_float4(0.f,0.f,0.f,0.f);
            __nv_bfloat16 h0,h1,h2,h3,l0,l1,l2,l3;
            split_bf(v.x,h0,l0); split_bf(v.y,h1,l1);
            split_bf(v.z,h2,l2); split_bf(v.w,h3,l3);
            int off = row*STR + cb + c;
            *(uint32_t*)(A_hi+off)   = pack_bf2(h0,h1);
            *(uint32_t*)(A_hi+off+2) = pack_bf2(h2,h3);
            *(uint32_t*)(A_lo+off)   = pack_bf2(l0,l1);
            *(uint32_t*)(A_lo+off+2) = pack_bf2(l2,l3);
        }
    }
    // ---- convert W1 fp32 -> bf16 hi/lo ----
    {
        int row = tid >> 1;
        int cb  = (tid & 1) * 64;
        const float* src = W1g + (size_t)row*HH + cb;
#pragma unroll
        for (int c = 0; c < 64; c += 4) {
            float4 v = *(const float4*)(src + c);
            __nv_bfloat16 h0,h1,h2,h3,l0,l1,l2,l3;
            split_bf(v.x,h0,l0); split_bf(v.y,h1,l1);
            split_bf(v.z,h2,l2); split_bf(v.w,h3,l3);
            int off = row*STR + cb + c;
            *(uint32_t*)(W_hi+off)   = pack_bf2(h0,h1);
            *(uint32_t*)(W_hi+off+2) = pack_bf2(h2,h3);
            *(uint32_t*)(W_lo+off)   = pack_bf2(l0,l1);
            *(uint32_t*)(W_lo+off+2) = pack_bf2(l2,l3);
        }
    }
    __syncthreads();

    float acc[2][8][4];
#pragma unroll
    for (int mt = 0; mt < 2; mt++)
#pragma unroll
        for (int nt = 0; nt < 8; nt++)
#pragma unroll
            for (int r = 0; r < 4; r++) acc[mt][nt][r] = 0.f;

    // ================= stage 1 mainloop =================
#pragma unroll
    for (int k0 = 0; k0 < 128; k0 += 16) {
        uint32_t ah[2][4], al[2][4];
#pragma unroll
        for (int mt = 0; mt < 2; mt++) {
            int off = (warpM*32 + mt*16 + (lane & 15))*STR + k0 + (lane >> 4)*8;
            ldmx4(ah[mt], sptr(A_hi + off));
            ldmx4(al[mt], sptr(A_lo + off));
        }
#pragma unroll
        for (int p = 0; p < 4; p++) {
            int off = (k0 + (lane & 15))*STR + warpN*64 + p*16 + (lane >> 4)*8;
            uint32_t bh[4], bl[4];
            ldmx4t(bh, sptr(W_hi + off));
            ldmx4t(bl, sptr(W_lo + off));
#pragma unroll
            for (int mt = 0; mt < 2; mt++) {
#pragma unroll
                for (int j = 0; j < 2; j++) {
                    int nt = 2*p + j;
                    mma16816(acc[mt][nt], ah[mt], bh + 2*j);
                    mma16816(acc[mt][nt], ah[mt], bl + 2*j);
                    mma16816(acc[mt][nt], al[mt], bh + 2*j);
                }
            }
        }
    }
    __syncthreads();   // all warps done reading A (h1 overwrites it) and W1

    // ---- epilogue 1: h1 = relu(acc + b1) -> bf16 hi/lo back into A bufs ----
#pragma unroll
    for (int mt = 0; mt < 2; mt++) {
        int r0 = warpM*32 + mt*16 + (lane >> 2);
#pragma unroll
        for (int nt = 0; nt < 8; nt++) {
            int c = warpN*64 + nt*8 + (lane & 3)*2;
            float bb0 = __ldg(bias1 + c), bb1 = __ldg(bias1 + c + 1);
            float v00 = fmaxf(acc[mt][nt][0] + bb0, 0.f);
            float v01 = fmaxf(acc[mt][nt][1] + bb1, 0.f);
            float v10 = fmaxf(acc[mt][nt][2] + bb0, 0.f);
            float v11 = fmaxf(acc[mt][nt][3] + bb1, 0.f);
            __nv_bfloat16 h0,h1,l0,l1;
            split_bf(v00,h0,l0); split_bf(v01,h1,l1);
            *(uint32_t*)(A_hi + r0*STR + c) = pack_bf2(h0,h1);
            *(uint32_t*)(A_lo + r0*STR + c) = pack_bf2(l0,l1);
            split_bf(v10,h0,l0); split_bf(v11,h1,l1);
            *(uint32_t*)(A_hi + (r0+8)*STR + c) = pack_bf2(h0,h1);
            *(uint32_t*)(A_lo + (r0+8)*STR + c) = pack_bf2(l0,l1);
        }
    }
    // ---- convert W2 (overwrite W bufs) ----
    {
        int row = tid >> 1;
        int cb  = (tid & 1) * 64;
        const float* src = W2g + (size_t)row*HH + cb;
#pragma unroll
        for (int c = 0; c < 64; c += 4) {
            float4 v = *(const float4*)(src + c);
            __nv_bfloat16 h0,h1,h2,h3,l0,l1,l2,l3;
            split_bf(v.x,h0,l0); split_bf(v.y,h1,l1);
            split_bf(v.z,h2,l2); split_bf(v.w,h3,l3);
            int off = row*STR + cb + c;
            *(uint32_t*)(W_hi+off)   = pack_bf2(h0,h1);
            *(uint32_t*)(W_hi+off+2) = pack_bf2(h2,h3);
            *(uint32_t*)(W_lo+off)   = pack_bf2(l0,l1);
            *(uint32_t*)(W_lo+off+2) = pack_bf2(l2,l3);
        }
    }
    __syncthreads();

#pragma unroll
    for (int mt = 0; mt < 2; mt++)
#pragma unroll
        for (int nt = 0; nt < 8; nt++)
#pragma unroll
            for (int r = 0; r < 4; r++) acc[mt][nt][r] = 0.f;

    // ================= stage 2 mainloop =================
#pragma unroll
    for (int k0 = 0; k0 < 128; k0 += 16) {
        uint32_t ah[2][4], al[2][4];
#pragma unroll
        for (int mt = 0; mt < 2; mt++) {
            int off = (warpM*32 + mt*16 + (lane & 15))*STR + k0 + (lane >> 4)*8;
            ldmx4(ah[mt], sptr(A_hi + off));
            ldmx4(al[mt], sptr(A_lo + off));
        }
#pragma unroll
        for (int p = 0; p < 4; p++) {
            int off = (k0 + (lane & 15))*STR + warpN*64 + p*16 + (lane >> 4)*8;
            uint32_t bh[4], bl[4];
            ldmx4t(bh, sptr(W_hi + off));
            ldmx4t(bl, sptr(W_lo + off));
#pragma unroll
            for (int mt = 0; mt < 2; mt++) {
#pragma unroll
                for (int j = 0; j < 2; j++) {
                    int nt = 2*p + j;
                    mma16816(acc[mt][nt], ah[mt], bh + 2*j);
                    mma16816(acc[mt][nt], ah[mt], bl + 2*j);
                    mma16816(acc[mt][nt], al[mt], bh + 2*j);
                }
            }
        }
    }

    // ---- epilogue 2: v = relu(acc + b2) -> C + BN stats ----
    float cs[8][2], cq[8][2];
#pragma unroll
    for (int nt = 0; nt < 8; nt++) { cs[nt][0]=cs[nt][1]=cq[nt][0]=cq[nt][1]=0.f; }

#pragma unroll
    for (int mt = 0; mt < 2; mt++) {
        int r0 = warpM*32 + mt*16 + (lane >> 2);
        int gr0 = blockRow + r0;
        int gr1 = gr0 + 8;
#pragma unroll
        for (int nt = 0; nt < 8; nt++) {
            int c = warpN*64 + nt*8 + (lane & 3)*2;
            float bb0 = __ldg(bias2 + c), bb1 = __ldg(bias2 + c + 1);
            if (gr0 < NN) {
                float v0 = fmaxf(acc[mt][nt][0] + bb0, 0.f);
                float v1 = fmaxf(acc[mt][nt][1] + bb1, 0.f);
                *(float2*)(C + (size_t)gr0*HH + c) = make_float2(v0, v1);
                cs[nt][0] += v0; cq[nt][0] += v0*v0;
                cs[nt][1] += v1; cq[nt][1] += v1*v1;
            }
            if (gr1 < NN) {
                float v0 = fmaxf(acc[mt][nt][2] + bb0, 0.f);
                float v1 = fmaxf(acc[mt][nt][3] + bb1, 0.f);
                *(float2*)(C + (size_t)gr1*HH + c) = make_float2(v0, v1);
                cs[nt][0] += v0; cq[nt][0] += v0*v0;
                cs[nt][1] += v1; cq[nt][1] += v1*v1;
            }
        }
    }
    __syncthreads();   // ssum/ssq init long since visible; re-sync before atomics OK
#pragma unroll
    for (int nt = 0; nt < 8; nt++) {
        int c = warpN*64 + nt*8 + (lane & 3)*2;
        atomicAdd(&ssum[c],   cs[nt][0]);
        atomicAdd(&ssum[c+1], cs[nt][1]);
        atomicAdd(&ssq [c],   cq[nt][0]);
        atomicAdd(&ssq [c+1], cq[nt][1]);
    }
    __syncthreads();
    if (tid < 128) {
        atomicAdd(&g_bnsum[tid],     ssum[tid]);
        atomicAdd(&g_bnsum[128+tid], ssq [tid]);
    }
}

// ---------------- BN apply + x-out + pooled reduction ------------------------
__global__ void k_bn_pool(const int* __restrict__ batch,
                          const float* __restrict__ gamma,
                          const float* __restrict__ beta,
                          int l) {
    int idx = blockIdx.x * blockDim.x + threadIdx.x;  // over NN * 32
    if (idx >= NN*(HH/4)) return;
    int row = idx >> 5;
    int c4  = (idx & 31) * 4;
    const float inv = 1.0f / (float)NN;

    float4 h = *(const float4*)(g_h2 + (size_t)row*HH + c4);
    float hv[4] = {h.x, h.y, h.z, h.w};
    float vo[4];
#pragma unroll
    for (int t = 0; t < 4; t++) {
        int c = c4 + t;
        float mean = g_bnsum[c] * inv;
        float var  = g_bnsum[128+c] * inv - mean*mean;
        float rs   = rsqrtf(var + BN_EPS);
        vo[t] = (hv[t] - mean) * rs * gamma[l*HH + c] + beta[l*HH + c];
    }
    float4 o = make_float4(vo[0], vo[1], vo[2], vo[3]);
    *(float4*)(g_x + (size_t)row*HH + c4) = o;

    int b = batch[row];
    red_add_v4(g_pool + (size_t)b*ZIN + l*HH + c4, o);
    if (l == 0 && c4 == 0) atomicAdd(&g_cnt[b], 1.0f);
}

// ---------------- Head: MLP + log_softmax, one block per graph ---------------
__global__ __launch_bounds__(256)
void k_head(const float* __restrict__ emb,
            const float* __restrict__ l1w, const float* __restrict__ l1b,
            const float* __restrict__ l2w, const float* __restrict__ l2b,
            const float* __restrict__ l4w, const float* __restrict__ l4b,
            float* __restrict__ out) {
    __shared__ float zin[ZIN];
    __shared__ float z1[H1D];
    __shared__ float z2[HH];
    __shared__ float lg[CC];
    __shared__ float lse;

    int g = blockIdx.x, t = threadIdx.x;
    float cnt = fmaxf(g_cnt[g], 1.0f);
    for (int c = t; c < LH; c += 256) zin[c] = g_pool[g*ZIN + c] / cnt;
    if (t < EMBD) zin[LH + t] = emb[g*EMBD + t];
    __syncthreads();

    {
        float a = l1b[t];
        for (int k = 0; k < ZIN; k++) a += zin[k] * l1w[k*H1D + t];
        z1[t] = fmaxf(a, 0.f);
    }
    __syncthreads();
    if (t < HH) {
        float a = l2b[t];
        for (int k = 0; k < H1D; k++) a += z1[k] * l2w[k*HH + t];
        z2[t] = fmaxf(a, 0.f);
    }
    __syncthreads();
    if (t < CC) {
        float a = l4b[t];
        for (int k = 0; k < HH; k++) a += z2[k] * l4w[k*CC + t];
        lg[t] = a;
    }
    __syncthreads();
    if (t == 0) {
        float m = lg[0];
        for (int i = 1; i < CC; i++) m = fmaxf(m, lg[i]);
        float s = 0.f;
        for (int i = 0; i < CC; i++) s += expf(lg[i] - m);
        lse = m + logf(s);
    }
    __syncthreads();
    if (t < CC) out[g*CC + t] = lg[t] - lse;
}

// ---------------- launch -----------------------------------------------------
extern "C" void kernel_launch(void* const* d_in, const int* in_sizes, int n_in,
                              void* d_out, int out_size) {
    const float* x     = (const float*)d_in[0];
    const int*   ei    = (const int*)  d_in[1];   // int32 (JAX x64 disabled)
    const int*   batch = (const int*)  d_in[2];   // int32
    const float* emb   = (const float*)d_in[3];
    const float* eps   = (const float*)d_in[4];
    const float* W1    = (const float*)d_in[5];
    const float* b1    = (const float*)d_in[6];
    const float* W2    = (const float*)d_in[7];
    const float* b2    = (const float*)d_in[8];
    const float* gamma = (const float*)d_in[9];
    const float* beta  = (const float*)d_in[10];
    const float* l1w   = (const float*)d_in[11];
    const float* l1b   = (const float*)d_in[12];
    const float* l2w   = (const float*)d_in[13];
    const float* l2b   = (const float*)d_in[14];
    const float* l4w   = (const float*)d_in[15];
    const float* l4b   = (const float*)d_in[16];
    float* out = (float*)d_out;

    float *agg, *xb, *h2b;
    cudaGetSymbolAddress((void**)&agg, g_agg);
    cudaGetSymbolAddress((void**)&xb,  g_x);
    cudaGetSymbolAddress((void**)&h2b, g_h2);

    // smem: 4 bf16 tiles [128][STR] + 256 floats of stats
    const int SMEM = 4*128*STR*2 + 2*128*4;   // 140288 B
    static bool attr_set = false;
    if (!attr_set) {
        cudaFuncSetAttribute(k_gemm_fused,
                             cudaFuncAttributeMaxDynamicSharedMemorySize, SMEM);
        attr_set = true;
    }

    // ---- CSR build (every call; deterministic) ----
    k_zero_rp<<<(NN+1 + 255)/256, 256>>>();
    k_deg<<<(EE + 255)/256, 256>>>(ei);
    k_scan<<<1, 1024>>>();
    k_fill<<<(EE + 255)/256, 256>>>(ei);

    k_zero_pool<<<(GG*ZIN + 255)/256, 256>>>();

    for (int l = 0; l < LL; l++) {
        k_zero_bn<<<1, 256>>>();
        const float* xin = (l == 0) ? x : xb;
        k_gather<<<(NN*32 + 255)/256, 256>>>(xin, eps, l);
        k_gemm_fused<<<(NN + 127)/128, 256, SMEM>>>(
            agg, W1 + l*HH*HH, b1 + l*HH, W2 + l*HH*HH, b2 + l*HH, h2b);
        k_bn_pool<<<(NN*(HH/4) + 255)/256, 256>>>(batch, gamma, beta, l);
    }

    k_head<<<GG, 256>>>(emb, l1w, l1b, l2w, l2b, l4w, l4b, out);
}

// round 11
// speedup vs baseline: 1.0183x; 1.0183x over previous
#include <cuda_runtime.h>
#include <cuda_bf16.h>
#include <cstdint>

// Problem constants
#define NN   50000
#define EE   600000
#define HH   128
#define LL   4
#define GG   64
#define EMBD 64
#define CC   10
#define LH   (LL*HH)        // 512
#define ZIN  (LH+EMBD)      // 576
#define H1D  256            // 2*H
#define BN_EPS 1e-5f
#define STR  136            // smem row stride in bf16 elems (multiple of 8)

// ---------------- device scratch (static, allocation-guard safe) -------------
__device__ __align__(16) float g_agg[NN*HH];   // aggregated input of current layer
__device__ __align__(16) float g_x[NN*HH];     // layer output (next layer's x)
__device__ __align__(16) float g_h2[NN*HH];    // pre-BN activations
__device__ __align__(16) float g_bnsum[2*HH];  // per-col sum / sumsq
__device__ __align__(16) float g_pool[GG*ZIN]; // pooled sums
__device__ __align__(16) float g_cnt[GG];      // nodes per graph
// CSR (rebuilt every call — deterministic)
__device__ int g_rowptr[NN+1];
__device__ int g_cursor[NN];
__device__ int g_col[EE];

// ---------------- helpers ----------------------------------------------------
__device__ __forceinline__ void red_add_v4(float* p, float4 v) {
    asm volatile("red.global.add.v4.f32 [%0], {%1,%2,%3,%4};"
                 :: "l"(p), "f"(v.x), "f"(v.y), "f"(v.z), "f"(v.w)
                 : "memory");
}
__device__ __forceinline__ uint32_t sptr(const void* p) {
    return (uint32_t)__cvta_generic_to_shared(p);
}
__device__ __forceinline__ void ldmx4(uint32_t* r, uint32_t addr) {
    asm volatile("ldmatrix.sync.aligned.m8n8.x4.shared.b16 {%0,%1,%2,%3}, [%4];"
        : "=r"(r[0]), "=r"(r[1]), "=r"(r[2]), "=r"(r[3]) : "r"(addr));
}
__device__ __forceinline__ void ldmx4t(uint32_t* r, uint32_t addr) {
    asm volatile("ldmatrix.sync.aligned.m8n8.x4.trans.shared.b16 {%0,%1,%2,%3}, [%4];"
        : "=r"(r[0]), "=r"(r[1]), "=r"(r[2]), "=r"(r[3]) : "r"(addr));
}
__device__ __forceinline__ void mma16816(float* c, const uint32_t* a, const uint32_t* b) {
    asm volatile("mma.sync.aligned.m16n8k16.row.col.f32.bf16.bf16.f32 "
        "{%0,%1,%2,%3}, {%4,%5,%6,%7}, {%8,%9}, {%0,%1,%2,%3};"
        : "+f"(c[0]), "+f"(c[1]), "+f"(c[2]), "+f"(c[3])
        : "r"(a[0]), "r"(a[1]), "r"(a[2]), "r"(a[3]), "r"(b[0]), "r"(b[1]));
}
__device__ __forceinline__ uint32_t pack_bf2(__nv_bfloat16 lo16, __nv_bfloat16 hi16) {
    return ((uint32_t)__bfloat16_as_ushort(hi16) << 16) | __bfloat16_as_ushort(lo16);
}
// split x into bf16 hi + bf16 lo (x ≈ hi + lo)
__device__ __forceinline__ void split_bf(float x, __nv_bfloat16& h, __nv_bfloat16& l) {
    h = __float2bfloat16(x);
    l = __float2bfloat16(x - __bfloat162float(h));
}

// ---------------- zero / CSR build kernels -----------------------------------
__global__ void k_zero_pool() {
    int i = blockIdx.x * blockDim.x + threadIdx.x;
    if (i < GG*ZIN) g_pool[i] = 0.f;
    if (i < GG)     g_cnt[i]  = 0.f;
}
__global__ void k_zero_bn() {
    if (threadIdx.x < 2*HH) g_bnsum[threadIdx.x] = 0.f;
}
__global__ void k_zero_rp() {
    int i = blockIdx.x * blockDim.x + threadIdx.x;
    if (i < NN+1) g_rowptr[i] = 0;
}
__global__ void k_deg(const int* __restrict__ ei) {
    int e = blockIdx.x * blockDim.x + threadIdx.x;
    if (e < EE) atomicAdd(&g_rowptr[ei[EE + e] + 1], 1);
}
__global__ __launch_bounds__(1024)
void k_scan() {
    __shared__ int carry;
    __shared__ int warpsum[32];
    int tid = threadIdx.x, lane = tid & 31, w = tid >> 5;
    if (tid == 0) carry = 0;
    __syncthreads();
    for (int base = 0; base < NN+1; base += 1024) {
        int i = base + tid;
        int v = (i <= NN) ? g_rowptr[i] : 0;
        int s = v;
#pragma unroll
        for (int o = 1; o < 32; o <<= 1) {
            int t = __shfl_up_sync(0xFFFFFFFFu, s, o);
            if (lane >= o) s += t;
        }
        if (lane == 31) warpsum[w] = s;
        __syncthreads();
        if (w == 0) {
            int ws = warpsum[lane];
#pragma unroll
            for (int o = 1; o < 32; o <<= 1) {
                int t = __shfl_up_sync(0xFFFFFFFFu, ws, o);
                if (lane >= o) ws += t;
            }
            warpsum[lane] = ws;
        }
        __syncthreads();
        int incl = s + (w ? warpsum[w-1] : 0) + carry;
        if (i <= NN) g_rowptr[i] = incl;
        if (i <  NN) g_cursor[i] = incl;
        int total = warpsum[31] + carry;
        __syncthreads();
        if (tid == 0) carry = total;
        __syncthreads();
    }
}
__global__ void k_fill(const int* __restrict__ ei) {
    int e = blockIdx.x * blockDim.x + threadIdx.x;
    if (e >= EE) return;
    int d = ei[EE + e];
    int pos = atomicAdd(&g_cursor[d], 1);
    g_col[pos] = ei[e];
}

// ---------------- gather: agg[i] = (1+eps_l)*x[i] + sum_{j in nbr(i)} x[j] ---
__global__ void k_gather(const float* __restrict__ x,
                         const float* __restrict__ eps, int l) {
    int gtid = blockIdx.x * blockDim.x + threadIdx.x;
    int row  = gtid >> 5;
    int lane = gtid & 31;
    if (row >= NN) return;
    const float4* x4 = (const float4*)x;
    float s = 1.0f + eps[l];
    float4 acc = x4[(size_t)row*32 + lane];
    acc.x *= s; acc.y *= s; acc.z *= s; acc.w *= s;

    int e   = g_rowptr[row];
    int end = g_rowptr[row+1];
    for (; e + 1 < end; e += 2) {
        int s0 = g_col[e], s1 = g_col[e+1];
        float4 v0 = x4[(size_t)s0*32 + lane];
        float4 v1 = x4[(size_t)s1*32 + lane];
        acc.x += v0.x + v1.x;
        acc.y += v0.y + v1.y;
        acc.z += v0.z + v1.z;
        acc.w += v0.w + v1.w;
    }
    if (e < end) {
        int s0 = g_col[e];
        float4 v0 = x4[(size_t)s0*32 + lane];
        acc.x += v0.x; acc.y += v0.y; acc.z += v0.z; acc.w += v0.w;
    }
    *(float4*)(g_agg + (size_t)row*HH + lane*4) = acc;
}

// ---------------- fused double GEMM via bf16 tensor cores (3-term split) -----
// 512 threads = 16 warps (4x4), warp tile 32x32. All tiles resident:
// A hi/lo, W1 hi/lo, W2 hi/lo (6 x 34.8KB smem). h1 overwrites A between stages.
__global__ __launch_bounds__(512)
void k_gemm_fused(const float* __restrict__ A,
                  const float* __restrict__ W1g, const float* __restrict__ bias1,
                  const float* __restrict__ W2g, const float* __restrict__ bias2,
                  float* __restrict__ C) {
    extern __shared__ char smem_raw[];
    __nv_bfloat16* A_hi = (__nv_bfloat16*)smem_raw;          // [128][STR]
    __nv_bfloat16* A_lo = A_hi + 128*STR;
    __nv_bfloat16* W1h  = A_lo + 128*STR;
    __nv_bfloat16* W1l  = W1h + 128*STR;
    __nv_bfloat16* W2h  = W1l + 128*STR;
    __nv_bfloat16* W2l  = W2h + 128*STR;
    float* ssum = (float*)(W2l + 128*STR);                   // 128
    float* ssq  = ssum + 128;                                // 128

    const int tid  = threadIdx.x;
    const int lane = tid & 31;
    const int wid  = tid >> 5;
    const int warpM = wid & 3;         // rows warpM*32
    const int warpN = wid >> 2;        // cols warpN*32
    const int blockRow = blockIdx.x * 128;

    if (tid < 128) { ssum[tid] = 0.f; ssq[tid] = 0.f; }

    // ---- prologue: convert A, W1, W2 -> bf16 hi/lo (each thread: 1/4 row) ----
    {
        int row = tid >> 2;            // 0..127
        int cb  = (tid & 3) * 32;      // 0,32,64,96
        int off = row*STR + cb;

        int grow = blockRow + row;
        bool ok = (grow < NN);
        const float* srcA = A   + (size_t)grow*HH + cb;
        const float* src1 = W1g + (size_t)row*HH + cb;
        const float* src2 = W2g + (size_t)row*HH + cb;
#pragma unroll
        for (int c = 0; c < 32; c += 4) {
            float4 v = ok ? *(const float4*)(srcA + c) : make_float4(0.f,0.f,0.f,0.f);
            __nv_bfloat16 h0,h1,h2,h3,l0,l1,l2,l3;
            split_bf(v.x,h0,l0); split_bf(v.y,h1,l1);
            split_bf(v.z,h2,l2); split_bf(v.w,h3,l3);
            *(uint32_t*)(A_hi+off+c)   = pack_bf2(h0,h1);
            *(uint32_t*)(A_hi+off+c+2) = pack_bf2(h2,h3);
            *(uint32_t*)(A_lo+off+c)   = pack_bf2(l0,l1);
            *(uint32_t*)(A_lo+off+c+2) = pack_bf2(l2,l3);
        }
#pragma unroll
        for (int c = 0; c < 32; c += 4) {
            float4 v = *(const float4*)(src1 + c);
            __nv_bfloat16 h0,h1,h2,h3,l0,l1,l2,l3;
            split_bf(v.x,h0,l0); split_bf(v.y,h1,l1);
            split_bf(v.z,h2,l2); split_bf(v.w,h3,l3);
            *(uint32_t*)(W1h+off+c)   = pack_bf2(h0,h1);
            *(uint32_t*)(W1h+off+c+2) = pack_bf2(h2,h3);
            *(uint32_t*)(W1l+off+c)   = pack_bf2(l0,l1);
            *(uint32_t*)(W1l+off+c+2) = pack_bf2(l2,l3);
        }
#pragma unroll
        for (int c = 0; c < 32; c += 4) {
            float4 v = *(const float4*)(src2 + c);
            __nv_bfloat16 h0,h1,h2,h3,l0,l1,l2,l3;
            split_bf(v.x,h0,l0); split_bf(v.y,h1,l1);
            split_bf(v.z,h2,l2); split_bf(v.w,h3,l3);
            *(uint32_t*)(W2h+off+c)   = pack_bf2(h0,h1);
            *(uint32_t*)(W2h+off+c+2) = pack_bf2(h2,h3);
            *(uint32_t*)(W2l+off+c)   = pack_bf2(l0,l1);
            *(uint32_t*)(W2l+off+c+2) = pack_bf2(l2,l3);
        }
    }
    __syncthreads();

    float acc[2][4][4];
#pragma unroll
    for (int mt = 0; mt < 2; mt++)
#pragma unroll
        for (int nt = 0; nt < 4; nt++)
#pragma unroll
            for (int r = 0; r < 4; r++) acc[mt][nt][r] = 0.f;

    // ================= stage 1 mainloop =================
#pragma unroll
    for (int k0 = 0; k0 < 128; k0 += 16) {
        uint32_t ah[2][4], al[2][4];
#pragma unroll
        for (int mt = 0; mt < 2; mt++) {
            int off = (warpM*32 + mt*16 + (lane & 15))*STR + k0 + (lane >> 4)*8;
            ldmx4(ah[mt], sptr(A_hi + off));
            ldmx4(al[mt], sptr(A_lo + off));
        }
#pragma unroll
        for (int p = 0; p < 2; p++) {
            int off = (k0 + (lane & 15))*STR + warpN*32 + p*16 + (lane >> 4)*8;
            uint32_t bh[4], bl[4];
            ldmx4t(bh, sptr(W1h + off));
            ldmx4t(bl, sptr(W1l + off));
#pragma unroll
            for (int mt = 0; mt < 2; mt++) {
#pragma unroll
                for (int j = 0; j < 2; j++) {
                    int nt = 2*p + j;
                    mma16816(acc[mt][nt], ah[mt], bh + 2*j);
                    mma16816(acc[mt][nt], ah[mt], bl + 2*j);
                    mma16816(acc[mt][nt], al[mt], bh + 2*j);
                }
            }
        }
    }
    __syncthreads();   // all warps done reading A (h1 overwrites it)

    // ---- epilogue 1: h1 = relu(acc + b1) -> bf16 hi/lo back into A bufs ----
#pragma unroll
    for (int mt = 0; mt < 2; mt++) {
        int r0 = warpM*32 + mt*16 + (lane >> 2);
#pragma unroll
        for (int nt = 0; nt < 4; nt++) {
            int c = warpN*32 + nt*8 + (lane & 3)*2;
            float bb0 = __ldg(bias1 + c), bb1 = __ldg(bias1 + c + 1);
            float v00 = fmaxf(acc[mt][nt][0] + bb0, 0.f);
            float v01 = fmaxf(acc[mt][nt][1] + bb1, 0.f);
            float v10 = fmaxf(acc[mt][nt][2] + bb0, 0.f);
            float v11 = fmaxf(acc[mt][nt][3] + bb1, 0.f);
            __nv_bfloat16 h0,h1,l0,l1;
            split_bf(v00,h0,l0); split_bf(v01,h1,l1);
            *(uint32_t*)(A_hi + r0*STR + c) = pack_bf2(h0,h1);
            *(uint32_t*)(A_lo + r0*STR + c) = pack_bf2(l0,l1);
            split_bf(v10,h0,l0); split_bf(v11,h1,l1);
            *(uint32_t*)(A_hi + (r0+8)*STR + c) = pack_bf2(h0,h1);
            *(uint32_t*)(A_lo + (r0+8)*STR + c) = pack_bf2(l0,l1);
        }
    }
    __syncthreads();

#pragma unroll
    for (int mt = 0; mt < 2; mt++)
#pragma unroll
        for (int nt = 0; nt < 4; nt++)
#pragma unroll
            for (int r = 0; r < 4; r++) acc[mt][nt][r] = 0.f;

    // ================= stage 2 mainloop =================
#pragma unroll
    for (int k0 = 0; k0 < 128; k0 += 16) {
        uint32_t ah[2][4], al[2][4];
#pragma unroll
        for (int mt = 0; mt < 2; mt++) {
            int off = (warpM*32 + mt*16 + (lane & 15))*STR + k0 + (lane >> 4)*8;
            ldmx4(ah[mt], sptr(A_hi + off));
            ldmx4(al[mt], sptr(A_lo + off));
        }
#pragma unroll
        for (int p = 0; p < 2; p++) {
            int off = (k0 + (lane & 15))*STR + warpN*32 + p*16 + (lane >> 4)*8;
            uint32_t bh[4], bl[4];
            ldmx4t(bh, sptr(W2h + off));
            ldmx4t(bl, sptr(W2l + off));
#pragma unroll
            for (int mt = 0; mt < 2; mt++) {
#pragma unroll
                for (int j = 0; j < 2; j++) {
                    int nt = 2*p + j;
                    mma16816(acc[mt][nt], ah[mt], bh + 2*j);
                    mma16816(acc[mt][nt], ah[mt], bl + 2*j);
                    mma16816(acc[mt][nt], al[mt], bh + 2*j);
                }
            }
        }
    }

    // ---- epilogue 2: v = relu(acc + b2) -> C + BN stats ----
    float cs[4][2], cq[4][2];
#pragma unroll
    for (int nt = 0; nt < 4; nt++) { cs[nt][0]=cs[nt][1]=cq[nt][0]=cq[nt][1]=0.f; }

#pragma unroll
    for (int mt = 0; mt < 2; mt++) {
        int r0 = warpM*32 + mt*16 + (lane >> 2);
        int gr0 = blockRow + r0;
        int gr1 = gr0 + 8;
#pragma unroll
        for (int nt = 0; nt < 4; nt++) {
            int c = warpN*32 + nt*8 + (lane & 3)*2;
            float bb0 = __ldg(bias2 + c), bb1 = __ldg(bias2 + c + 1);
            if (gr0 < NN) {
                float v0 = fmaxf(acc[mt][nt][0] + bb0, 0.f);
                float v1 = fmaxf(acc[mt][nt][1] + bb1, 0.f);
                *(float2*)(C + (size_t)gr0*HH + c) = make_float2(v0, v1);
                cs[nt][0] += v0; cq[nt][0] += v0*v0;
                cs[nt][1] += v1; cq[nt][1] += v1*v1;
            }
            if (gr1 < NN) {
                float v0 = fmaxf(acc[mt][nt][2] + bb0, 0.f);
                float v1 = fmaxf(acc[mt][nt][3] + bb1, 0.f);
                *(float2*)(C + (size_t)gr1*HH + c) = make_float2(v0, v1);
                cs[nt][0] += v0; cq[nt][0] += v0*v0;
                cs[nt][1] += v1; cq[nt][1] += v1*v1;
            }
        }
    }
    __syncthreads();
#pragma unroll
    for (int nt = 0; nt < 4; nt++) {
        int c = warpN*32 + nt*8 + (lane & 3)*2;
        atomicAdd(&ssum[c],   cs[nt][0]);
        atomicAdd(&ssum[c+1], cs[nt][1]);
        atomicAdd(&ssq [c],   cq[nt][0]);
        atomicAdd(&ssq [c+1], cq[nt][1]);
    }
    __syncthreads();
    if (tid < 128) {
        atomicAdd(&g_bnsum[tid],     ssum[tid]);
        atomicAdd(&g_bnsum[128+tid], ssq [tid]);
    }
}

// ---------------- BN apply + x-out + pooled reduction ------------------------
__global__ void k_bn_pool(const int* __restrict__ batch,
                          const float* __restrict__ gamma,
                          const float* __restrict__ beta,
                          int l) {
    int idx = blockIdx.x * blockDim.x + threadIdx.x;  // over NN * 32
    if (idx >= NN*(HH/4)) return;
    int row = idx >> 5;
    int c4  = (idx & 31) * 4;
    const float inv = 1.0f / (float)NN;

    float4 h = *(const float4*)(g_h2 + (size_t)row*HH + c4);
    float hv[4] = {h.x, h.y, h.z, h.w};
    float vo[4];
#pragma unroll
    for (int t = 0; t < 4; t++) {
        int c = c4 + t;
        float mean = g_bnsum[c] * inv;
        float var  = g_bnsum[128+c] * inv - mean*mean;
        float rs   = rsqrtf(var + BN_EPS);
        vo[t] = (hv[t] - mean) * rs * gamma[l*HH + c] + beta[l*HH + c];
    }
    float4 o = make_float4(vo[0], vo[1], vo[2], vo[3]);
    *(float4*)(g_x + (size_t)row*HH + c4) = o;

    int b = batch[row];
    red_add_v4(g_pool + (size_t)b*ZIN + l*HH + c4, o);
    if (l == 0 && c4 == 0) atomicAdd(&g_cnt[b], 1.0f);
}

// ---------------- Head: MLP + log_softmax, one block per graph ---------------
__global__ __launch_bounds__(256)
void k_head(const float* __restrict__ emb,
            const float* __restrict__ l1w, const float* __restrict__ l1b,
            const float* __restrict__ l2w, const float* __restrict__ l2b,
            const float* __restrict__ l4w, const float* __restrict__ l4b,
            float* __restrict__ out) {
    __shared__ float zin[ZIN];
    __shared__ float z1[H1D];
    __shared__ float z2[HH];
    __shared__ float lg[CC];
    __shared__ float lse;

    int g = blockIdx.x, t = threadIdx.x;
    float cnt = fmaxf(g_cnt[g], 1.0f);
    for (int c = t; c < LH; c += 256) zin[c] = g_pool[g*ZIN + c] / cnt;
    if (t < EMBD) zin[LH + t] = emb[g*EMBD + t];
    __syncthreads();

    {
        float a = l1b[t];
        for (int k = 0; k < ZIN; k++) a += zin[k] * l1w[k*H1D + t];
        z1[t] = fmaxf(a, 0.f);
    }
    __syncthreads();
    if (t < HH) {
        float a = l2b[t];
        for (int k = 0; k < H1D; k++) a += z1[k] * l2w[k*HH + t];
        z2[t] = fmaxf(a, 0.f);
    }
    __syncthreads();
    if (t < CC) {
        float a = l4b[t];
        for (int k = 0; k < HH; k++) a += z2[k] * l4w[k*CC + t];
        lg[t] = a;
    }
    __syncthreads();
    if (t == 0) {
        float m = lg[0];
        for (int i = 1; i < CC; i++) m = fmaxf(m, lg[i]);
        float s = 0.f;
        for (int i = 0; i < CC; i++) s += expf(lg[i] - m);
        lse = m + logf(s);
    }
    __syncthreads();
    if (t < CC) out[g*CC + t] = lg[t] - lse;
}

// ---------------- launch -----------------------------------------------------
extern "C" void kernel_launch(void* const* d_in, const int* in_sizes, int n_in,
                              void* d_out, int out_size) {
    const float* x     = (const float*)d_in[0];
    const int*   ei    = (const int*)  d_in[1];   // int32 (JAX x64 disabled)
    const int*   batch = (const int*)  d_in[2];   // int32
    const float* emb   = (const float*)d_in[3];
    const float* eps   = (const float*)d_in[4];
    const float* W1    = (const float*)d_in[5];
    const float* b1    = (const float*)d_in[6];
    const float* W2    = (const float*)d_in[7];
    const float* b2    = (const float*)d_in[8];
    const float* gamma = (const float*)d_in[9];
    const float* beta  = (const float*)d_in[10];
    const float* l1w   = (const float*)d_in[11];
    const float* l1b   = (const float*)d_in[12];
    const float* l2w   = (const float*)d_in[13];
    const float* l2b   = (const float*)d_in[14];
    const float* l4w   = (const float*)d_in[15];
    const float* l4b   = (const float*)d_in[16];
    float* out = (float*)d_out;

    float *agg, *xb, *h2b;
    cudaGetSymbolAddress((void**)&agg, g_agg);
    cudaGetSymbolAddress((void**)&xb,  g_x);
    cudaGetSymbolAddress((void**)&h2b, g_h2);

    // smem: 6 bf16 tiles [128][STR] + 256 floats of stats = 209920 B
    const int SMEM = 6*128*STR*2 + 2*128*4;
    static bool attr_set = false;
    if (!attr_set) {
        cudaFuncSetAttribute(k_gemm_fused,
                             cudaFuncAttributeMaxDynamicSharedMemorySize, SMEM);
        attr_set = true;
    }

    // ---- CSR build (every call; deterministic) ----
    k_zero_rp<<<(NN+1 + 255)/256, 256>>>();
    k_deg<<<(EE + 255)/256, 256>>>(ei);
    k_scan<<<1, 1024>>>();
    k_fill<<<(EE + 255)/256, 256>>>(ei);

    k_zero_pool<<<(GG*ZIN + 255)/256, 256>>>();

    for (int l = 0; l < LL; l++) {
        k_zero_bn<<<1, 256>>>();
        const float* xin = (l == 0) ? x : xb;
        k_gather<<<(NN*32 + 255)/256, 256>>>(xin, eps, l);
        k_gemm_fused<<<(NN + 127)/128, 512, SMEM>>>(
            agg, W1 + l*HH*HH, b1 + l*HH, W2 + l*HH*HH, b2 + l*HH, h2b);
        k_bn_pool<<<(NN*(HH/4) + 255)/256, 256>>>(batch, gamma, beta, l);
    }

    k_head<<<GG, 256>>>(emb, l1w, l1b, l2w, l2b, l4w, l4b, out);
}

// round 12
// speedup vs baseline: 1.0659x; 1.0467x over previous
#include <cuda_runtime.h>

// Problem constants
#define NN   50000
#define EE   600000
#define HH   128
#define LL   4
#define GG   64
#define EMBD 64
#define CC   10
#define LH   (LL*HH)        // 512
#define ZIN  (LH+EMBD)      // 576
#define H1D  256            // 2*H
#define BN_EPS 1e-5f

// ---------------- device scratch (static, allocation-guard safe) -------------
__device__ __align__(16) float g_agg[NN*HH];   // aggregated input of current layer
__device__ __align__(16) float g_h2[NN*HH];    // pre-BN activations (layer output)
__device__ __align__(16) float g_bnsum[2*HH];  // per-col sum / sumsq
__device__ __align__(16) float g_bna[LH];      // per-layer BN affine scale a
__device__ __align__(16) float g_bnd[LH];      // per-layer BN affine shift d
__device__ __align__(16) float g_pool[GG*LH];  // pooled h2 sums per graph
__device__ __align__(16) float g_cnt[GG];      // nodes per graph
// CSR (rebuilt every call — deterministic)
__device__ int g_rowptr[NN+1];
__device__ int g_cursor[NN];
__device__ int g_col[EE];

// ---------------- vectorized global reduction --------------------------------
__device__ __forceinline__ void red_add_v4(float* p, float4 v) {
    asm volatile("red.global.add.v4.f32 [%0], {%1,%2,%3,%4};"
                 :: "l"(p), "f"(v.x), "f"(v.y), "f"(v.z), "f"(v.w)
                 : "memory");
}

// ---------------- zero / CSR build kernels -----------------------------------
__global__ void k_zero_pool() {
    int i = blockIdx.x * blockDim.x + threadIdx.x;
    if (i < GG*LH) g_pool[i] = 0.f;
}
__global__ void k_zero_bn() {
    if (threadIdx.x < 2*HH) g_bnsum[threadIdx.x] = 0.f;
}
__global__ void k_zero_rp() {
    int i = blockIdx.x * blockDim.x + threadIdx.x;
    if (i < NN+1) g_rowptr[i] = 0;
}
__global__ void k_deg(const int* __restrict__ ei) {
    int e = blockIdx.x * blockDim.x + threadIdx.x;
    if (e < EE) atomicAdd(&g_rowptr[ei[EE + e] + 1], 1);
}
__global__ __launch_bounds__(1024)
void k_scan() {
    __shared__ int carry;
    __shared__ int warpsum[32];
    int tid = threadIdx.x, lane = tid & 31, w = tid >> 5;
    if (tid == 0) carry = 0;
    __syncthreads();
    for (int base = 0; base < NN+1; base += 1024) {
        int i = base + tid;
        int v = (i <= NN) ? g_rowptr[i] : 0;
        int s = v;
#pragma unroll
        for (int o = 1; o < 32; o <<= 1) {
            int t = __shfl_up_sync(0xFFFFFFFFu, s, o);
            if (lane >= o) s += t;
        }
        if (lane == 31) warpsum[w] = s;
        __syncthreads();
        if (w == 0) {
            int ws = warpsum[lane];
#pragma unroll
            for (int o = 1; o < 32; o <<= 1) {
                int t = __shfl_up_sync(0xFFFFFFFFu, ws, o);
                if (lane >= o) ws += t;
            }
            warpsum[lane] = ws;
        }
        __syncthreads();
        int incl = s + (w ? warpsum[w-1] : 0) + carry;
        if (i <= NN) g_rowptr[i] = incl;
        if (i <  NN) g_cursor[i] = incl;
        int total = warpsum[31] + carry;
        __syncthreads();
        if (tid == 0) carry = total;
        __syncthreads();
    }
}
__global__ void k_fill(const int* __restrict__ ei) {
    int e = blockIdx.x * blockDim.x + threadIdx.x;
    if (e >= EE) return;
    int d = ei[EE + e];
    int pos = atomicAdd(&g_cursor[d], 1);
    g_col[pos] = ei[e];
}
// nodes per graph via binary search on sorted batch
__global__ void k_cnt(const int* __restrict__ batch) {
    int g = threadIdx.x;
    if (g >= GG) return;
    int lo = 0, hi = NN;
    while (lo < hi) { int m = (lo+hi) >> 1; if (batch[m] < g) lo = m+1; else hi = m; }
    int first = lo;
    lo = 0; hi = NN;
    while (lo < hi) { int m = (lo+hi) >> 1; if (batch[m] < g+1) lo = m+1; else hi = m; }
    g_cnt[g] = (float)(lo - first);
}

// ---------------- BN affine constants for layer l ----------------------------
__global__ void k_bnaff(const float* __restrict__ gamma,
                        const float* __restrict__ beta, int l) {
    int c = threadIdx.x;
    if (c >= HH) return;
    const float inv = 1.0f / (float)NN;
    float mean = g_bnsum[c] * inv;
    float var  = g_bnsum[HH+c] * inv - mean*mean;
    float a = gamma[l*HH + c] * rsqrtf(var + BN_EPS);
    g_bna[l*HH + c] = a;
    g_bnd[l*HH + c] = beta[l*HH + c] - mean * a;
}

// ---------------- gather + fused BN of previous layer ------------------------
// l==0: agg_i = (1+eps0)*x_i + sum_j x_j   (src = raw input x)
// l>0 : src = h2 of prev layer; x = a*h2 + d (BN affine), so
//       agg_i = a*((1+eps)*h_i + sum h_j) + d*((1+eps) + deg_i)
__global__ void k_gather(const float* __restrict__ src,
                         const float* __restrict__ eps, int l) {
    int gtid = blockIdx.x * blockDim.x + threadIdx.x;
    int row  = gtid >> 5;
    int lane = gtid & 31;
    if (row >= NN) return;
    const float4* x4 = (const float4*)src;
    float s = 1.0f + eps[l];
    float4 acc = x4[(size_t)row*32 + lane];
    acc.x *= s; acc.y *= s; acc.z *= s; acc.w *= s;

    int e0  = g_rowptr[row];
    int end = g_rowptr[row+1];
    int e = e0;
    for (; e + 1 < end; e += 2) {
        int s0 = g_col[e], s1 = g_col[e+1];
        float4 v0 = x4[(size_t)s0*32 + lane];
        float4 v1 = x4[(size_t)s1*32 + lane];
        acc.x += v0.x + v1.x;
        acc.y += v0.y + v1.y;
        acc.z += v0.z + v1.z;
        acc.w += v0.w + v1.w;
    }
    if (e < end) {
        int s0 = g_col[e];
        float4 v0 = x4[(size_t)s0*32 + lane];
        acc.x += v0.x; acc.y += v0.y; acc.z += v0.z; acc.w += v0.w;
    }
    if (l > 0) {
        float4 a = *(const float4*)(g_bna + (l-1)*HH + lane*4);
        float4 d = *(const float4*)(g_bnd + (l-1)*HH + lane*4);
        float t = s + (float)(end - e0);
        acc.x = fmaf(a.x, acc.x, d.x*t);
        acc.y = fmaf(a.y, acc.y, d.y*t);
        acc.z = fmaf(a.z, acc.z, d.z*t);
        acc.w = fmaf(a.w, acc.w, d.w*t);
    }
    *(float4*)(g_agg + (size_t)row*HH + lane*4) = acc;
}

// ---------------- fused double SGEMM + BN stats + h2 pooling -----------------
// h1 = relu(A @ W1 + b1)  (kept in smem), C = relu(h1 @ W2 + b2).
// Epilogue also: per-column sum/sumsq (BN stats) and per-graph pooled h2 sums.
// BM=128, BN=128, BK=16, 256 threads, 8x8 per thread.
__global__ __launch_bounds__(256)
void k_gemm_fused(const float* __restrict__ A,
                  const float* __restrict__ W1, const float* __restrict__ b1,
                  const float* __restrict__ W2, const float* __restrict__ b2,
                  float* __restrict__ C,
                  const int* __restrict__ batch, int l) {
    extern __shared__ float smem[];
    float (*As)[128] = (float(*)[128])smem;                  // 16x128
    float (*Bs)[128] = (float(*)[128])(smem + 16*128);       // 16x128
    float (*Hs)[132] = (float(*)[132])(smem + 2*16*128);     // 128x132 (padded)
    float* ssum = smem + 2*16*128 + 128*132;                 // 128
    float* ssq  = ssum + 128;                                // 128

    int tid = threadIdx.x;
    int blockRow = blockIdx.x * 128;

    int aRow  = tid >> 2;          // 0..63
    int aCol4 = (tid & 3) * 4;     // 0,4,8,12
    int bRow  = tid >> 5;          // 0..7
    int bCol4 = (tid & 31) * 4;    // 0..124

    int tr = (tid >> 4) * 8;       // 0..120
    int tc = (tid & 15) * 8;       // 0..120

    if (tid < 128) { ssum[tid] = 0.f; ssq[tid] = 0.f; }

    float acc[8][8];
#pragma unroll
    for (int i = 0; i < 8; i++)
#pragma unroll
        for (int j = 0; j < 8; j++) acc[i][j] = 0.f;

    // -------- stage 1: acc = A @ W1 --------
    for (int k0 = 0; k0 < 128; k0 += 16) {
#pragma unroll
        for (int i = 0; i < 2; i++) {
            int r = blockRow + aRow + i*64;
            float4 v = make_float4(0.f,0.f,0.f,0.f);
            if (r < NN) v = *(const float4*)(A + (size_t)r*HH + k0 + aCol4);
            As[aCol4+0][aRow + i*64] = v.x;
            As[aCol4+1][aRow + i*64] = v.y;
            As[aCol4+2][aRow + i*64] = v.z;
            As[aCol4+3][aRow + i*64] = v.w;
        }
#pragma unroll
        for (int i = 0; i < 2; i++) {
            float4 v = *(const float4*)(W1 + (size_t)(k0 + bRow + i*8)*128 + bCol4);
            *(float4*)(&Bs[bRow + i*8][bCol4]) = v;
        }
        __syncthreads();
#pragma unroll
        for (int k = 0; k < 16; k++) {
            float ra[8], rb[8];
            float4 a0 = *(const float4*)(&As[k][tr]);
            float4 a1 = *(const float4*)(&As[k][tr+4]);
            float4 bb0 = *(const float4*)(&Bs[k][tc]);
            float4 bb1 = *(const float4*)(&Bs[k][tc+4]);
            ra[0]=a0.x; ra[1]=a0.y; ra[2]=a0.z; ra[3]=a0.w;
            ra[4]=a1.x; ra[5]=a1.y; ra[6]=a1.z; ra[7]=a1.w;
            rb[0]=bb0.x; rb[1]=bb0.y; rb[2]=bb0.z; rb[3]=bb0.w;
            rb[4]=bb1.x; rb[5]=bb1.y; rb[6]=bb1.z; rb[7]=bb1.w;
#pragma unroll
            for (int i = 0; i < 8; i++)
#pragma unroll
                for (int j = 0; j < 8; j++)
                    acc[i][j] += ra[i]*rb[j];
        }
        __syncthreads();
    }

    // epilogue 1: bias+relu, park h1 tile in smem
    {
        float rb1[8];
#pragma unroll
        for (int j = 0; j < 8; j++) rb1[j] = b1[tc+j];
#pragma unroll
        for (int i = 0; i < 8; i++) {
            float4 v0, v1;
            v0.x = fmaxf(acc[i][0] + rb1[0], 0.f);
            v0.y = fmaxf(acc[i][1] + rb1[1], 0.f);
            v0.z = fmaxf(acc[i][2] + rb1[2], 0.f);
            v0.w = fmaxf(acc[i][3] + rb1[3], 0.f);
            v1.x = fmaxf(acc[i][4] + rb1[4], 0.f);
            v1.y = fmaxf(acc[i][5] + rb1[5], 0.f);
            v1.z = fmaxf(acc[i][6] + rb1[6], 0.f);
            v1.w = fmaxf(acc[i][7] + rb1[7], 0.f);
            *(float4*)(&Hs[tr+i][tc])   = v0;
            *(float4*)(&Hs[tr+i][tc+4]) = v1;
        }
    }
    __syncthreads();

    // -------- stage 2: acc = Hs @ W2 --------
#pragma unroll
    for (int i = 0; i < 8; i++)
#pragma unroll
        for (int j = 0; j < 8; j++) acc[i][j] = 0.f;

    for (int k0 = 0; k0 < 128; k0 += 16) {
#pragma unroll
        for (int i = 0; i < 2; i++) {
            float4 v = *(const float4*)(W2 + (size_t)(k0 + bRow + i*8)*128 + bCol4);
            *(float4*)(&Bs[bRow + i*8][bCol4]) = v;
        }
        __syncthreads();
#pragma unroll
        for (int k = 0; k < 16; k++) {
            float ra[8], rb[8];
            float4 bb0 = *(const float4*)(&Bs[k][tc]);
            float4 bb1 = *(const float4*)(&Bs[k][tc+4]);
            rb[0]=bb0.x; rb[1]=bb0.y; rb[2]=bb0.z; rb[3]=bb0.w;
            rb[4]=bb1.x; rb[5]=bb1.y; rb[6]=bb1.z; rb[7]=bb1.w;
#pragma unroll
            for (int i = 0; i < 8; i++) ra[i] = Hs[tr+i][k0+k];
#pragma unroll
            for (int i = 0; i < 8; i++)
#pragma unroll
                for (int j = 0; j < 8; j++)
                    acc[i][j] += ra[i]*rb[j];
        }
        __syncthreads();
    }

    // epilogue 2: bias+relu, store C, BN stats, pooled h2 reds
    float rb2[8];
#pragma unroll
    for (int j = 0; j < 8; j++) rb2[j] = b2[tc+j];

    float csum[8], csq[8];
#pragma unroll
    for (int j = 0; j < 8; j++) { csum[j]=0.f; csq[j]=0.f; }

#pragma unroll
    for (int i = 0; i < 8; i++) {
        int r = blockRow + tr + i;
        if (r < NN) {
            float v[8];
#pragma unroll
            for (int j = 0; j < 8; j++) {
                v[j] = fmaxf(acc[i][j] + rb2[j], 0.f);
                csum[j] += v[j]; csq[j] += v[j]*v[j];
            }
            float4 q0 = make_float4(v[0],v[1],v[2],v[3]);
            float4 q1 = make_float4(v[4],v[5],v[6],v[7]);
            *(float4*)(C + (size_t)r*HH + tc)     = q0;
            *(float4*)(C + (size_t)r*HH + tc + 4) = q1;
            int b = batch[r];
            float* pp = g_pool + (size_t)b*LH + l*HH + tc;
            red_add_v4(pp,     q0);
            red_add_v4(pp + 4, q1);
        }
    }

    __syncthreads();
#pragma unroll
    for (int j = 0; j < 8; j++) {
        atomicAdd(&ssum[tc+j], csum[j]);
        atomicAdd(&ssq [tc+j], csq [j]);
    }
    __syncthreads();
    if (tid < 128) {
        atomicAdd(&g_bnsum[tid],    ssum[tid]);
        atomicAdd(&g_bnsum[HH+tid], ssq [tid]);
    }
}

// ---------------- Head: affine on pooled h2, MLP + log_softmax ---------------
__global__ __launch_bounds__(256)
void k_head(const float* __restrict__ emb,
            const float* __restrict__ l1w, const float* __restrict__ l1b,
            const float* __restrict__ l2w, const float* __restrict__ l2b,
            const float* __restrict__ l4w, const float* __restrict__ l4b,
            float* __restrict__ out) {
    __shared__ float zin[ZIN];
    __shared__ float z1[H1D];
    __shared__ float z2[HH];
    __shared__ float lg[CC];
    __shared__ float lse;

    int g = blockIdx.x, t = threadIdx.x;
    float cnt = fmaxf(g_cnt[g], 1.0f);
    // pooled x mean = a * (pooled h2)/cnt + d
    for (int c = t; c < LH; c += 256)
        zin[c] = fmaf(g_bna[c], g_pool[g*LH + c] / cnt, g_bnd[c]);
    if (t < EMBD) zin[LH + t] = emb[g*EMBD + t];
    __syncthreads();

    {
        float a = l1b[t];
        for (int k = 0; k < ZIN; k++) a += zin[k] * l1w[k*H1D + t];
        z1[t] = fmaxf(a, 0.f);
    }
    __syncthreads();
    if (t < HH) {
        float a = l2b[t];
        for (int k = 0; k < H1D; k++) a += z1[k] * l2w[k*HH + t];
        z2[t] = fmaxf(a, 0.f);
    }
    __syncthreads();
    if (t < CC) {
        float a = l4b[t];
        for (int k = 0; k < HH; k++) a += z2[k] * l4w[k*CC + t];
        lg[t] = a;
    }
    __syncthreads();
    if (t == 0) {
        float m = lg[0];
        for (int i = 1; i < CC; i++) m = fmaxf(m, lg[i]);
        float s = 0.f;
        for (int i = 0; i < CC; i++) s += expf(lg[i] - m);
        lse = m + logf(s);
    }
    __syncthreads();
    if (t < CC) out[g*CC + t] = lg[t] - lse;
}

// ---------------- launch -----------------------------------------------------
extern "C" void kernel_launch(void* const* d_in, const int* in_sizes, int n_in,
                              void* d_out, int out_size) {
    const float* x     = (const float*)d_in[0];
    const int*   ei    = (const int*)  d_in[1];   // int32 (JAX x64 disabled)
    const int*   batch = (const int*)  d_in[2];   // int32
    const float* emb   = (const float*)d_in[3];
    const float* eps   = (const float*)d_in[4];
    const float* W1    = (const float*)d_in[5];
    const float* b1    = (const float*)d_in[6];
    const float* W2    = (const float*)d_in[7];
    const float* b2    = (const float*)d_in[8];
    const float* gamma = (const float*)d_in[9];
    const float* beta  = (const float*)d_in[10];
    const float* l1w   = (const float*)d_in[11];
    const float* l1b   = (const float*)d_in[12];
    const float* l2w   = (const float*)d_in[13];
    const float* l2b   = (const float*)d_in[14];
    const float* l4w   = (const float*)d_in[15];
    const float* l4b   = (const float*)d_in[16];
    float* out = (float*)d_out;

    float *agg, *h2b;
    cudaGetSymbolAddress((void**)&agg, g_agg);
    cudaGetSymbolAddress((void**)&h2b, g_h2);

    const int SMEM = (2*16*128 + 128*132 + 256) * 4;   // ~85 KB
    static bool attr_set = false;
    if (!attr_set) {
        cudaFuncSetAttribute(k_gemm_fused,
                             cudaFuncAttributeMaxDynamicSharedMemorySize, SMEM);
        attr_set = true;
    }

    // ---- CSR build (every call; deterministic) ----
    k_zero_rp<<<(NN+1 + 255)/256, 256>>>();
    k_deg<<<(EE + 255)/256, 256>>>(ei);
    k_scan<<<1, 1024>>>();
    k_fill<<<(EE + 255)/256, 256>>>(ei);

    k_zero_pool<<<(GG*LH + 255)/256, 256>>>();
    k_cnt<<<1, GG>>>(batch);

    for (int l = 0; l < LL; l++) {
        const float* src = (l == 0) ? x : h2b;
        k_gather<<<(NN*32 + 255)/256, 256>>>(src, eps, l);
        k_zero_bn<<<1, 256>>>();
        k_gemm_fused<<<(NN + 127)/128, 256, SMEM>>>(
            agg, W1 + l*HH*HH, b1 + l*HH, W2 + l*HH*HH, b2 + l*HH, h2b,
            batch, l);
        k_bnaff<<<1, HH>>>(gamma, beta, l);
    }

    k_head<<<GG, 256>>>(emb, l1w, l1b, l2w, l2b, l4w, l4b, out);
}